// round 3
// baseline (speedup 1.0000x reference)
#include <cuda_runtime.h>
#include <stdint.h>

#define Bb 32
#define Nn 512
#define Ll 8
#define Kk 8
#define MS 64
#define SP 68    // 64x64 shared stride: %32=4 (conflict-free), *4B %16=0 (LDS.128 ok)
#define AS 132   // 64x128 shared stride: %32=4, *4B %16=0

// ---------------- scratch (static device globals) ---------------------------
__device__ float  g_M[Bb][MS][MS];
__device__ float  g_P[Bb][MS][MS];      // M^T diag(~w) M
__device__ float  g_DRR[Bb][MS][MS];
__device__ float  g_G2[Bb][MS][MS];
__device__ float  g_DcolT[Bb][Nn][MS];  // DcolT[b][c][s] = Dstrip[s][c]
__device__ float  g_AcolT[Bb][Nn][MS];
__device__ int8_t g_slotof[Bb][Nn];
__device__ int    g_slots[Bb][MS];
__device__ int8_t g_wflag[Bb][MS];
__device__ int    g_m[Bb];

// ---------------- packed f32x2 helpers --------------------------------------
typedef unsigned long long ull;

__device__ __forceinline__ ull pack2(float x) {
    ull r; asm("mov.b64 %0, {%1, %1};" : "=l"(r) : "f"(x)); return r;
}
__device__ __forceinline__ void ffma2(ull& d, ull a, ull b) {
    asm("fma.rn.f32x2 %0, %1, %2, %3;" : "=l"(d) : "l"(a), "l"(b), "l"(d));
}
__device__ __forceinline__ void unpack2(ull v, float& lo, float& hi) {
    asm("mov.b64 {%0, %1}, %2;" : "=f"(lo), "=f"(hi) : "l"(v));
}

// C = A @ B (64x64, stride SP), 512 threads: 1 row x 8 cols per thread
__device__ __forceinline__ void gemm64x(const float* __restrict__ Am,
                                        const float* __restrict__ Bm,
                                        float* __restrict__ Cm, int tid) {
    const int i = tid >> 3, j0 = (tid & 7) * 8;
    ull a0 = 0, a1 = 0, a2 = 0, a3 = 0;
    #pragma unroll 8
    for (int k = 0; k < 64; k++) {
        ull pa = pack2(Am[i * SP + k]);
        ulonglong2 b01 = *(const ulonglong2*)&Bm[k * SP + j0];
        ulonglong2 b23 = *(const ulonglong2*)&Bm[k * SP + j0 + 4];
        ffma2(a0, pa, b01.x); ffma2(a1, pa, b01.y);
        ffma2(a2, pa, b23.x); ffma2(a3, pa, b23.y);
    }
    ulonglong2 s0; s0.x = a0; s0.y = a1;
    ulonglong2 s1; s1.x = a2; s1.y = a3;
    *(ulonglong2*)&Cm[i * SP + j0]     = s0;
    *(ulonglong2*)&Cm[i * SP + j0 + 4] = s1;
}

// ---------------- K1: per-batch setup (512 threads) -------------------------
#define K1_SMEM ((4 * 64 * SP + 512) * 4)

__global__ void __launch_bounds__(512) mmf_k1(const float* __restrict__ A,
                                              const float* __restrict__ O,
                                              const int* __restrict__ idx,
                                              const int* __restrict__ wav) {
    extern __shared__ float sm[];
    float* Msh  = sm;
    float* MTsh = sm + 64 * SP;
    float* T1   = sm + 2 * 64 * SP;
    float* T2   = sm + 3 * 64 * SP;
    float* tmp  = sm + 4 * 64 * SP;     // 512 floats

    __shared__ int slotof[Nn];
    __shared__ int slots[MS], val[MS], isf[MS], fpos[MS], pslot[MS], wflag[MS];
    __shared__ int rs[Kk];
    __shared__ float Osh[Kk * Kk];

    const int b = blockIdx.x;
    const int tid = threadIdx.x;

    slotof[tid] = -1;                    // 512 threads, Nn=512
    if (tid < MS) { wflag[tid] = 0; slots[tid] = 0; val[tid] = idx[b * MS + tid]; }
    __syncthreads();

    // parallel first-occurrence dedup
    if (tid < MS) {
        int v = val[tid], fp = 0;
        while (val[fp] != v) fp++;
        fpos[tid] = fp;
        isf[tid] = (fp == tid) ? 1 : 0;
    }
    __syncthreads();
    if (tid < MS) {
        int s = 0, fp = fpos[tid];
        for (int q = 0; q < fp; q++) s += isf[q];
        pslot[tid] = s;
        if (isf[tid]) { slots[s] = val[tid]; slotof[val[tid]] = s; }
    }
    __syncthreads();
    if (tid < Ll) wflag[slotof[wav[b * Ll + tid]]] = 1;
    if (tid == 0) {
        int m = 0;
        #pragma unroll
        for (int q = 0; q < MS; q++) m += isf[q];
        g_m[b] = m;
    }
    __syncthreads();

    // M = I
    for (int e = tid; e < 4096; e += 512) {
        int i = e >> 6, j = e & 63;
        Msh[i * SP + j] = (i == j) ? 1.f : 0.f;
    }
    __syncthreads();

    // layer updates: rows pslot(l,:) <- O_l @ those rows
    for (int l = 0; l < Ll; l++) {
        if (tid < Kk) rs[tid] = pslot[l * Kk + tid];
        if (tid < Kk * Kk) Osh[tid] = O[((size_t)l * Bb + b) * Kk * Kk + tid];
        __syncthreads();
        {
            int i = tid >> 6, c = tid & 63;   // 8 rows x 64 cols = 512
            float s = 0.f;
            #pragma unroll
            for (int j = 0; j < Kk; j++) s += Osh[i * Kk + j] * Msh[rs[j] * SP + c];
            tmp[tid] = s;
        }
        __syncthreads();
        Msh[rs[tid >> 6] * SP + (tid & 63)] = tmp[tid];
        __syncthreads();
    }

    // MT + publish
    for (int e = tid; e < 4096; e += 512) {
        int i = e >> 6, j = e & 63;
        float v = Msh[i * SP + j];
        MTsh[j * SP + i] = v;
        g_M[b][i][j] = v;
    }
    g_slotof[b][tid] = (int8_t)slotof[tid];
    if (tid < MS) {
        g_slots[b][tid] = slots[tid];
        g_wflag[b][tid] = (int8_t)wflag[tid];
    }

    // T1 = A_RR gather
    for (int e = tid; e < 4096; e += 512) {
        int i = e >> 6, j = e & 63;
        T1[i * SP + j] = A[((size_t)b * Nn + slots[i]) * Nn + slots[j]];
    }
    __syncthreads();

    gemm64x(Msh, T1, T2, tid);  __syncthreads();   // X = M A_RR
    gemm64x(T2, MTsh, T1, tid); __syncthreads();   // F_RR = X M^T

    for (int e = tid; e < 4096; e += 512) {        // D_RR = mask(F_RR)
        int i = e >> 6, j = e & 63;
        float v = T1[i * SP + j];
        if (i != j && (wflag[i] || wflag[j])) v = 0.f;
        T1[i * SP + j] = v;
        g_DRR[b][i][j] = v;
    }
    __syncthreads();

    gemm64x(MTsh, T1, T2, tid); __syncthreads();   // M^T D_RR
    gemm64x(T2, Msh, T1, tid);  __syncthreads();   // G2

    for (int e = tid; e < 4096; e += 512)
        g_G2[b][e >> 6][e & 63] = T1[(e >> 6) * SP + (e & 63)];

    // Mw = diag(~w) M  -> T2
    for (int e = tid; e < 4096; e += 512) {
        int i = e >> 6, j = e & 63;
        T2[i * SP + j] = wflag[i] ? 0.f : Msh[i * SP + j];
    }
    __syncthreads();
    gemm64x(MTsh, T2, T1, tid); __syncthreads();   // P = M^T Mw
    for (int e = tid; e < 4096; e += 512)
        g_P[b][e >> 6][e & 63] = T1[(e >> 6) * SP + (e & 63)];
}

// ---------------- K2: strip dual-GEMM per 128-col tile (128 CTAs) -----------
#define K2_SMEM ((2 * 64 * SP + 3 * 64 * AS) * 4)

__global__ void __launch_bounds__(512) mmf_k2(const float* __restrict__ A,
                                              float* __restrict__ out) {
    extern __shared__ float sm2[];
    float* Msh = sm2;
    float* Psh = sm2 + 64 * SP;
    float* At  = sm2 + 2 * 64 * SP;          // A strip tile 64x128
    float* Dsh = At + 64 * AS;
    float* Esh = Dsh + 64 * AS;

    __shared__ int    slots[MS];
    __shared__ int8_t wfl[MS];
    __shared__ int8_t slc[128];
    __shared__ int    mS;

    const int b  = blockIdx.y;
    const int c0 = blockIdx.x * 128;
    const int tid = threadIdx.x;

    for (int e = tid; e < 4096; e += 512) {
        int i = e >> 6, j = e & 63;
        Msh[i * SP + j] = g_M[b][i][j];
        Psh[i * SP + j] = g_P[b][i][j];
    }
    if (tid < MS) { slots[tid] = g_slots[b][tid]; wfl[tid] = g_wflag[b][tid]; }
    if (tid >= 128 && tid < 256) slc[tid - 128] = g_slotof[b][c0 + (tid - 128)];
    if (tid == 0) mS = g_m[b];
    __syncthreads();

    // gather A strip tile (rows = slots)
    {
        int k = tid >> 3, cq = (tid & 7) * 16;
        const float* src = &A[((size_t)b * Nn + slots[k]) * Nn + c0 + cq];
        #pragma unroll
        for (int q = 0; q < 4; q++)
            *(float4*)&At[k * AS + cq + 4 * q] = *(const float4*)&src[4 * q];
    }
    __syncthreads();

    // fused dual GEMM: F = M @ At, E = P @ At (share B-operand loads)
    const int i = tid >> 3, j0 = (tid & 7) * 16;
    ull aF[8], aE[8];
    #pragma unroll
    for (int t = 0; t < 8; t++) { aF[t] = 0ULL; aE[t] = 0ULL; }

    #pragma unroll 4
    for (int k = 0; k < 64; k++) {
        ull pm = pack2(Msh[i * SP + k]);
        ull pp = pack2(Psh[i * SP + k]);
        ulonglong2 b0 = *(const ulonglong2*)&At[k * AS + j0];
        ulonglong2 b1 = *(const ulonglong2*)&At[k * AS + j0 + 4];
        ulonglong2 b2 = *(const ulonglong2*)&At[k * AS + j0 + 8];
        ulonglong2 b3 = *(const ulonglong2*)&At[k * AS + j0 + 12];
        ffma2(aF[0], pm, b0.x); ffma2(aF[1], pm, b0.y);
        ffma2(aF[2], pm, b1.x); ffma2(aF[3], pm, b1.y);
        ffma2(aF[4], pm, b2.x); ffma2(aF[5], pm, b2.y);
        ffma2(aF[6], pm, b3.x); ffma2(aF[7], pm, b3.y);
        ffma2(aE[0], pp, b0.x); ffma2(aE[1], pp, b0.y);
        ffma2(aE[2], pp, b1.x); ffma2(aE[3], pp, b1.y);
        ffma2(aE[4], pp, b2.x); ffma2(aE[5], pp, b2.y);
        ffma2(aE[6], pp, b3.x); ffma2(aE[7], pp, b3.y);
    }

    // substitution + strip-row output + staging (per 4-col chunk)
    const size_t MAT = (size_t)Bb * Nn * Nn;
    const size_t base = ((size_t)b * Nn + slots[i]) * Nn + c0 + j0;
    const bool strip = (i < mS);
    const float wz = wfl[i] ? 0.f : 1.f;

    #pragma unroll
    for (int ch = 0; ch < 4; ch++) {
        float f0, f1, f2, f3, e0, e1, e2, e3;
        unpack2(aF[2 * ch],     f0, f1);
        unpack2(aF[2 * ch + 1], f2, f3);
        unpack2(aE[2 * ch],     e0, e1);
        unpack2(aE[2 * ch + 1], e2, e3);
        float4 dv, av, rv;
        int c = j0 + 4 * ch;
        int s0 = slc[c], s1 = slc[c + 1], s2 = slc[c + 2], s3 = slc[c + 3];
        dv.x = (s0 >= 0) ? g_DRR[b][i][s0] : wz * f0;
        dv.y = (s1 >= 0) ? g_DRR[b][i][s1] : wz * f1;
        dv.z = (s2 >= 0) ? g_DRR[b][i][s2] : wz * f2;
        dv.w = (s3 >= 0) ? g_DRR[b][i][s3] : wz * f3;
        av.x = (s0 >= 0) ? g_G2[b][i][s0] : e0;
        av.y = (s1 >= 0) ? g_G2[b][i][s1] : e1;
        av.z = (s2 >= 0) ? g_G2[b][i][s2] : e2;
        av.w = (s3 >= 0) ? g_G2[b][i][s3] : e3;
        rv.x = (s0 >= 0) ? Msh[i * SP + s0] : 0.f;
        rv.y = (s1 >= 0) ? Msh[i * SP + s1] : 0.f;
        rv.z = (s2 >= 0) ? Msh[i * SP + s2] : 0.f;
        rv.w = (s3 >= 0) ? Msh[i * SP + s3] : 0.f;

        *(float4*)&Dsh[i * AS + c] = dv;
        *(float4*)&Esh[i * AS + c] = av;
        if (strip) {
            *(float4*)&out[base + 4 * ch]           = av;   // A_rec
            *(float4*)&out[MAT + base + 4 * ch]     = rv;   // right
            *(float4*)&out[2 * MAT + base + 4 * ch] = dv;   // D
        }
    }
    __syncthreads();

    // coalesced transposed copies for K3 column patching
    for (int e = tid; e < 8192; e += 512) {
        int cc = e >> 6, r = e & 63;
        g_DcolT[b][c0 + cc][r] = Dsh[r * AS + cc];
        g_AcolT[b][c0 + cc][r] = Esh[r * AS + cc];
    }
}

// ---------------- K3: non-strip rows assembly --------------------------------
__global__ void __launch_bounds__(512) mmf_k3(const float* __restrict__ A,
                                              float* __restrict__ out) {
    const int b    = blockIdx.y;
    const int i    = blockIdx.x * 4 + (threadIdx.x >> 7);
    const int lane = threadIdx.x & 127;
    const int c0   = lane * 4;

    if (g_slotof[b][i] >= 0) return;   // strip rows written by K2

    const size_t rowbase = ((size_t)b * Nn + i) * Nn + c0;
    const char4 sl = *(const char4*)(&g_slotof[b][c0]);

    float4 a = *(const float4*)(&A[rowbase]);
    float4 va = a, vd = a;
    const float* act = &g_AcolT[b][i][0];
    const float* dct = &g_DcolT[b][i][0];
    if (sl.x >= 0) { va.x = act[sl.x]; vd.x = dct[sl.x]; }
    if (sl.y >= 0) { va.y = act[sl.y]; vd.y = dct[sl.y]; }
    if (sl.z >= 0) { va.z = act[sl.z]; vd.z = dct[sl.z]; }
    if (sl.w >= 0) { va.w = act[sl.w]; vd.w = dct[sl.w]; }
    float4 vr = make_float4(0.f, 0.f, 0.f, 0.f);
    if (i >= c0 && i < c0 + 4) ((float*)&vr)[i - c0] = 1.f;

    const size_t MAT = (size_t)Bb * Nn * Nn;
    *(float4*)(&out[rowbase])           = va;
    *(float4*)(&out[MAT + rowbase])     = vr;
    *(float4*)(&out[2 * MAT + rowbase]) = vd;
}

// ---------------- launch ------------------------------------------------------
extern "C" void kernel_launch(void* const* d_in, const int* in_sizes, int n_in,
                              void* d_out, int out_size) {
    const float* A   = (const float*)d_in[0];
    const float* O   = (const float*)d_in[1];
    const int*   idx = (const int*)d_in[2];
    const int*   wav = (const int*)d_in[3];
    float* out = (float*)d_out;

    cudaFuncSetAttribute(mmf_k1, cudaFuncAttributeMaxDynamicSharedMemorySize, K1_SMEM);
    cudaFuncSetAttribute(mmf_k2, cudaFuncAttributeMaxDynamicSharedMemorySize, K2_SMEM);

    mmf_k1<<<Bb, 512, K1_SMEM>>>(A, O, idx, wav);
    mmf_k2<<<dim3(Nn / 128, Bb), 512, K2_SMEM>>>(A, out);
    mmf_k3<<<dim3(Nn / 4, Bb), 512>>>(A, out);
}

// round 4
// speedup vs baseline: 1.7315x; 1.7315x over previous
#include <cuda_runtime.h>
#include <stdint.h>

#define Bb 32
#define Nn 512
#define Ll 8
#define Kk 8
#define MS 64
#define SP 68    // 64-wide shared stride: conflict-free, 16B-aligned rows
#define AS 132   // 128-wide shared stride: conflict-free, 16B-aligned rows

// ---------------- scratch (static device globals) ---------------------------
__device__ float  g_MT[Bb][MS][MS];     // M^T
__device__ float  g_P[Bb][MS][MS];      // M^T diag(~w) M (symmetric)
__device__ float  g_DRR[Bb][MS][MS];
__device__ float  g_G2[Bb][MS][MS];
__device__ float  g_DcolT[Bb][Nn][MS];
__device__ float  g_AcolT[Bb][Nn][MS];
__device__ int8_t g_slotof[Bb][Nn];
__device__ int    g_slots[Bb][MS];
__device__ int8_t g_wflag[Bb][MS];
__device__ int    g_m[Bb];

// ---------------- packed f32x2 helpers --------------------------------------
typedef unsigned long long ull;

__device__ __forceinline__ ull pack2(float x) {
    ull r; asm("mov.b64 %0, {%1, %1};" : "=l"(r) : "f"(x)); return r;
}
__device__ __forceinline__ void ffma2(ull& d, ull a, ull b) {
    asm("fma.rn.f32x2 %0, %1, %2, %3;" : "=l"(d) : "l"(a), "l"(b), "l"(d));
}
__device__ __forceinline__ void unpack2(ull v, float& lo, float& hi) {
    asm("mov.b64 {%0, %1}, %2;" : "=f"(lo), "=f"(hi) : "l"(v));
}

// ---- C = A @ B (64x64). AT = A transposed (AT[k][i]); Bsh normal (B[k][j]).
// 256 threads: thread -> rows i0..i0+3, cols j0..j0+3. Conflict-free:
//   A: one LDS.128 broadcast per k; B: LDS.128 at 4*lane (128B/phase).
__device__ __forceinline__ void gemmAT256(const float* __restrict__ AT,
                                          const float* __restrict__ Bsh,
                                          float* __restrict__ Csh,
                                          int tid, bool transC) {
    const int i0 = (tid >> 4) * 4;
    const int j0 = (tid & 15) * 4;
    ull acc[4][2];
    #pragma unroll
    for (int r = 0; r < 4; r++) { acc[r][0] = 0ULL; acc[r][1] = 0ULL; }

    #pragma unroll 4
    for (int k = 0; k < 64; k++) {
        float4 aq = *(const float4*)&AT[k * SP + i0];
        ulonglong2 bq = *(const ulonglong2*)&Bsh[k * SP + j0];
        ull a0 = pack2(aq.x), a1 = pack2(aq.y), a2 = pack2(aq.z), a3 = pack2(aq.w);
        ffma2(acc[0][0], a0, bq.x); ffma2(acc[0][1], a0, bq.y);
        ffma2(acc[1][0], a1, bq.x); ffma2(acc[1][1], a1, bq.y);
        ffma2(acc[2][0], a2, bq.x); ffma2(acc[2][1], a2, bq.y);
        ffma2(acc[3][0], a3, bq.x); ffma2(acc[3][1], a3, bq.y);
    }
    if (!transC) {
        #pragma unroll
        for (int r = 0; r < 4; r++) {
            ulonglong2 s; s.x = acc[r][0]; s.y = acc[r][1];
            *(ulonglong2*)&Csh[(i0 + r) * SP + j0] = s;
        }
    } else {
        float v[4][4];
        #pragma unroll
        for (int r = 0; r < 4; r++) {
            unpack2(acc[r][0], v[r][0], v[r][1]);
            unpack2(acc[r][1], v[r][2], v[r][3]);
        }
        #pragma unroll
        for (int c = 0; c < 4; c++) {
            float4 col = make_float4(v[0][c], v[1][c], v[2][c], v[3][c]);
            *(float4*)&Csh[(j0 + c) * SP + i0] = col;
        }
    }
}

// ---------------- K1: per-batch setup, 5 small GEMMs (256 threads) ----------
#define K1_SMEM (6 * 64 * SP * 4)

__global__ void __launch_bounds__(256) mmf_k1(const float* __restrict__ A,
                                              const float* __restrict__ O,
                                              const int* __restrict__ idx,
                                              const int* __restrict__ wav) {
    extern __shared__ float sm[];
    float* Msh  = sm;
    float* MTsh = sm + 1 * 64 * SP;
    float* WMsh = sm + 2 * 64 * SP;
    float* BufA = sm + 3 * 64 * SP;
    float* BufB = sm + 4 * 64 * SP;
    float* BufC = sm + 5 * 64 * SP;

    __shared__ int slotof[Nn];
    __shared__ int slots[MS], val[MS], isf[MS], fpos[MS], pslot[MS], wflag[MS];
    __shared__ int rs[Kk];
    __shared__ float Osh[Kk * Kk];
    __shared__ float tmp[Kk * 64];

    const int b = blockIdx.x;
    const int tid = threadIdx.x;

    for (int j = tid; j < Nn; j += 256) slotof[j] = -1;
    if (tid < MS) { wflag[tid] = 0; slots[tid] = 0; val[tid] = idx[b * MS + tid]; }
    __syncthreads();

    // parallel first-occurrence dedup
    if (tid < MS) {
        int v = val[tid], fp = 0;
        while (val[fp] != v) fp++;
        fpos[tid] = fp;
        isf[tid] = (fp == tid) ? 1 : 0;
    }
    __syncthreads();
    if (tid < MS) {
        int s = 0, fp = fpos[tid];
        for (int q = 0; q < fp; q++) s += isf[q];
        pslot[tid] = s;
        if (isf[tid]) { slots[s] = val[tid]; slotof[val[tid]] = s; }
    }
    __syncthreads();
    if (tid < Ll) wflag[slotof[wav[b * Ll + tid]]] = 1;
    if (tid == 0) {
        int m = 0;
        #pragma unroll
        for (int q = 0; q < MS; q++) m += isf[q];
        g_m[b] = m;
    }
    __syncthreads();

    // M = I
    for (int e = tid; e < 4096; e += 256) {
        int i = e >> 6, j = e & 63;
        Msh[i * SP + j] = (i == j) ? 1.f : 0.f;
    }
    __syncthreads();

    // layer updates: rows pslot(l,:) <- O_l @ those rows
    for (int l = 0; l < Ll; l++) {
        if (tid < Kk) rs[tid] = pslot[l * Kk + tid];
        if (tid < Kk * Kk) Osh[tid] = O[((size_t)l * Bb + b) * Kk * Kk + tid];
        __syncthreads();
        for (int e = tid; e < Kk * 64; e += 256) {
            int i = e >> 6, c = e & 63;
            float s = 0.f;
            #pragma unroll
            for (int j = 0; j < Kk; j++) s += Osh[i * Kk + j] * Msh[rs[j] * SP + c];
            tmp[e] = s;
        }
        __syncthreads();
        for (int e = tid; e < Kk * 64; e += 256)
            Msh[rs[e >> 6] * SP + (e & 63)] = tmp[e];
        __syncthreads();
    }

    // MT + WM + publish maps
    for (int e = tid; e < 4096; e += 256) {
        int i = e >> 6, j = e & 63;
        float v = Msh[i * SP + j];
        MTsh[j * SP + i] = v;
        WMsh[i * SP + j] = wflag[i] ? 0.f : v;
        g_MT[b][j][i] = v;
    }
    for (int j = tid; j < Nn; j += 256) g_slotof[b][j] = (int8_t)slotof[j];
    if (tid < MS) {
        g_slots[b][tid] = slots[tid];
        g_wflag[b][tid] = (int8_t)wflag[tid];
    }

    // BufA = A_RR gather
    for (int e = tid; e < 4096; e += 256) {
        int i = e >> 6, j = e & 63;
        BufA[i * SP + j] = A[((size_t)b * Nn + slots[i]) * Nn + slots[j]];
    }
    __syncthreads();

    // gemm1: X = M @ A_RR      (AT = MT, B = ARR)  -> BufB stores X^T
    gemmAT256(MTsh, BufA, BufB, tid, true);  __syncthreads();
    // gemm2: F = X @ M^T       (AT = X^T, B = MT)  -> BufC normal
    gemmAT256(BufB, MTsh, BufC, tid, false); __syncthreads();

    // mask -> D_RR (in place, symmetric)
    for (int e = tid; e < 4096; e += 256) {
        int i = e >> 6, j = e & 63;
        float v = BufC[i * SP + j];
        if (i != j && (wflag[i] || wflag[j])) v = 0.f;
        BufC[i * SP + j] = v;
        g_DRR[b][i][j] = v;
    }
    __syncthreads();

    // gemm3: T = D @ M         (D symmetric: AT = D, B = M) -> BufA
    gemmAT256(BufC, Msh, BufA, tid, false);  __syncthreads();
    // gemm4: G2 = M^T @ T      (AT = M, B = T)  -> BufB
    gemmAT256(Msh, BufA, BufB, tid, false);  __syncthreads();
    for (int e = tid; e < 4096; e += 256)
        g_G2[b][e >> 6][e & 63] = BufB[(e >> 6) * SP + (e & 63)];

    // gemm5: P = (WrM)^T @ M   (AT = WM, B = M)  -> BufC
    gemmAT256(WMsh, Msh, BufC, tid, false);  __syncthreads();
    for (int e = tid; e < 4096; e += 256)
        g_P[b][e >> 6][e & 63] = BufC[(e >> 6) * SP + (e & 63)];
}

// ---------------- K2: strip dual-GEMM per 128-col tile (128 CTAs, 512 thr) --
#define K2_SMEM ((2 * 64 * SP + 3 * 64 * AS) * 4)

__global__ void __launch_bounds__(512) mmf_k2(const float* __restrict__ A,
                                              float* __restrict__ out) {
    extern __shared__ float sm2[];
    float* MTsh = sm2;
    float* Psh  = sm2 + 64 * SP;
    float* At   = sm2 + 2 * 64 * SP;
    float* Dsh  = At + 64 * AS;
    float* Esh  = Dsh + 64 * AS;

    __shared__ int    slots[MS];
    __shared__ int8_t wfl[MS];
    __shared__ int8_t slc[128];
    __shared__ int    mS;

    const int b  = blockIdx.y;
    const int c0 = blockIdx.x * 128;
    const int tid = threadIdx.x;

    for (int e = tid; e < 4096; e += 512) {
        int i = e >> 6, j = e & 63;
        MTsh[i * SP + j] = g_MT[b][i][j];
        Psh[i * SP + j]  = g_P[b][i][j];    // symmetric
    }
    if (tid < MS) { slots[tid] = g_slots[b][tid]; wfl[tid] = g_wflag[b][tid]; }
    if (tid >= 128 && tid < 256) slc[tid - 128] = g_slotof[b][c0 + (tid - 128)];
    if (tid == 0) mS = g_m[b];
    __syncthreads();

    // gather A strip tile (rows = slots), 64 x 128
    {
        int k = tid >> 3, cq = (tid & 7) * 16;
        const float* src = &A[((size_t)b * Nn + slots[k]) * Nn + c0 + cq];
        #pragma unroll
        for (int q = 0; q < 4; q++)
            *(float4*)&At[k * AS + cq + 4 * q] = *(const float4*)&src[4 * q];
    }
    __syncthreads();

    // dual GEMM: F = M @ At (via MT quads), E = P @ At (P symmetric)
    // thread: rows i0..i0+3 (warp-uniform), cols j0..j0+3
    const int i0 = (tid >> 5) * 4;
    const int j0 = (tid & 31) * 4;
    ull aF[4][2], aE[4][2];
    #pragma unroll
    for (int r = 0; r < 4; r++) {
        aF[r][0] = aF[r][1] = 0ULL;
        aE[r][0] = aE[r][1] = 0ULL;
    }

    #pragma unroll 4
    for (int k = 0; k < 64; k++) {
        float4 mq = *(const float4*)&MTsh[k * SP + i0];   // broadcast
        float4 pq = *(const float4*)&Psh[k * SP + i0];    // broadcast
        ulonglong2 bq = *(const ulonglong2*)&At[k * AS + j0];
        ull m0 = pack2(mq.x), m1 = pack2(mq.y), m2 = pack2(mq.z), m3 = pack2(mq.w);
        ull p0 = pack2(pq.x), p1 = pack2(pq.y), p2 = pack2(pq.z), p3 = pack2(pq.w);
        ffma2(aF[0][0], m0, bq.x); ffma2(aF[0][1], m0, bq.y);
        ffma2(aF[1][0], m1, bq.x); ffma2(aF[1][1], m1, bq.y);
        ffma2(aF[2][0], m2, bq.x); ffma2(aF[2][1], m2, bq.y);
        ffma2(aF[3][0], m3, bq.x); ffma2(aF[3][1], m3, bq.y);
        ffma2(aE[0][0], p0, bq.x); ffma2(aE[0][1], p0, bq.y);
        ffma2(aE[1][0], p1, bq.x); ffma2(aE[1][1], p1, bq.y);
        ffma2(aE[2][0], p2, bq.x); ffma2(aE[2][1], p2, bq.y);
        ffma2(aE[3][0], p3, bq.x); ffma2(aE[3][1], p3, bq.y);
    }

    // substitution + strip-row output + staging
    const size_t MAT = (size_t)Bb * Nn * Nn;
    const int s0 = slc[j0], s1 = slc[j0 + 1], s2 = slc[j0 + 2], s3 = slc[j0 + 3];

    #pragma unroll
    for (int r = 0; r < 4; r++) {
        const int i = i0 + r;
        const float wz = wfl[i] ? 0.f : 1.f;
        float f0, f1, f2, f3, e0, e1, e2, e3;
        unpack2(aF[r][0], f0, f1); unpack2(aF[r][1], f2, f3);
        unpack2(aE[r][0], e0, e1); unpack2(aE[r][1], e2, e3);

        float4 dv, av, rv;
        dv.x = (s0 >= 0) ? g_DRR[b][i][s0] : wz * f0;
        dv.y = (s1 >= 0) ? g_DRR[b][i][s1] : wz * f1;
        dv.z = (s2 >= 0) ? g_DRR[b][i][s2] : wz * f2;
        dv.w = (s3 >= 0) ? g_DRR[b][i][s3] : wz * f3;
        av.x = (s0 >= 0) ? g_G2[b][i][s0] : e0;
        av.y = (s1 >= 0) ? g_G2[b][i][s1] : e1;
        av.z = (s2 >= 0) ? g_G2[b][i][s2] : e2;
        av.w = (s3 >= 0) ? g_G2[b][i][s3] : e3;
        rv.x = (s0 >= 0) ? MTsh[s0 * SP + i] : 0.f;
        rv.y = (s1 >= 0) ? MTsh[s1 * SP + i] : 0.f;
        rv.z = (s2 >= 0) ? MTsh[s2 * SP + i] : 0.f;
        rv.w = (s3 >= 0) ? MTsh[s3 * SP + i] : 0.f;

        *(float4*)&Dsh[i * AS + j0] = dv;
        *(float4*)&Esh[i * AS + j0] = av;
        if (i < mS) {
            const size_t base = ((size_t)b * Nn + slots[i]) * Nn + c0 + j0;
            *(float4*)&out[base]           = av;   // A_rec
            *(float4*)&out[MAT + base]     = rv;   // right
            *(float4*)&out[2 * MAT + base] = dv;   // D
        }
    }
    __syncthreads();

    // coalesced transposed copies for K3 column patching
    for (int e = tid; e < 8192; e += 512) {
        int cc = e >> 6, rr = e & 63;
        g_DcolT[b][c0 + cc][rr] = Dsh[rr * AS + cc];
        g_AcolT[b][c0 + cc][rr] = Esh[rr * AS + cc];
    }
}

// ---------------- K3: non-strip rows assembly --------------------------------
__global__ void __launch_bounds__(512) mmf_k3(const float* __restrict__ A,
                                              float* __restrict__ out) {
    const int b    = blockIdx.y;
    const int i    = blockIdx.x * 4 + (threadIdx.x >> 7);
    const int lane = threadIdx.x & 127;
    const int c0   = lane * 4;

    if (g_slotof[b][i] >= 0) return;   // strip rows written by K2

    const size_t rowbase = ((size_t)b * Nn + i) * Nn + c0;
    const char4 sl = *(const char4*)(&g_slotof[b][c0]);

    float4 a = *(const float4*)(&A[rowbase]);
    float4 va = a, vd = a;
    const float* act = &g_AcolT[b][i][0];
    const float* dct = &g_DcolT[b][i][0];
    if (sl.x >= 0) { va.x = act[sl.x]; vd.x = dct[sl.x]; }
    if (sl.y >= 0) { va.y = act[sl.y]; vd.y = dct[sl.y]; }
    if (sl.z >= 0) { va.z = act[sl.z]; vd.z = dct[sl.z]; }
    if (sl.w >= 0) { va.w = act[sl.w]; vd.w = dct[sl.w]; }
    float4 vr = make_float4(0.f, 0.f, 0.f, 0.f);
    if (i >= c0 && i < c0 + 4) ((float*)&vr)[i - c0] = 1.f;

    const size_t MAT = (size_t)Bb * Nn * Nn;
    *(float4*)(&out[rowbase])           = va;
    *(float4*)(&out[MAT + rowbase])     = vr;
    *(float4*)(&out[2 * MAT + rowbase]) = vd;
}

// ---------------- launch ------------------------------------------------------
extern "C" void kernel_launch(void* const* d_in, const int* in_sizes, int n_in,
                              void* d_out, int out_size) {
    const float* A   = (const float*)d_in[0];
    const float* O   = (const float*)d_in[1];
    const int*   idx = (const int*)d_in[2];
    const int*   wav = (const int*)d_in[3];
    float* out = (float*)d_out;

    cudaFuncSetAttribute(mmf_k1, cudaFuncAttributeMaxDynamicSharedMemorySize, K1_SMEM);
    cudaFuncSetAttribute(mmf_k2, cudaFuncAttributeMaxDynamicSharedMemorySize, K2_SMEM);

    mmf_k1<<<Bb, 256, K1_SMEM>>>(A, O, idx, wav);
    mmf_k2<<<dim3(Nn / 128, Bb), 512, K2_SMEM>>>(A, out);
    mmf_k3<<<dim3(Nn / 4, Bb), 512>>>(A, out);
}

// round 5
// speedup vs baseline: 2.0227x; 1.1682x over previous
#include <cuda_runtime.h>
#include <stdint.h>

#define Bb 32
#define Nn 512
#define Ll 8
#define Kk 8
#define MS 64
#define SP 68    // 64-wide shared stride: conflict-free, 16B-aligned rows
#define AS 132   // 128-wide shared stride: conflict-free, 16B-aligned rows

// ---------------- scratch (static device globals) ---------------------------
__device__ float  g_MT[Bb][MS][MS];     // M^T
__device__ float  g_P[Bb][MS][MS];      // M^T diag(~w) M (symmetric)
__device__ float  g_DRR[Bb][MS][MS];
__device__ float  g_G2[Bb][MS][MS];
__device__ float  g_DcolT[Bb][Nn][MS];
__device__ float  g_AcolT[Bb][Nn][MS];
__device__ int8_t g_slotof[Bb][Nn];
__device__ int    g_slots[Bb][MS];
__device__ int8_t g_wflag[Bb][MS];
__device__ int    g_m[Bb];

// ---------------- packed f32x2 helpers --------------------------------------
typedef unsigned long long ull;

__device__ __forceinline__ ull pack2(float x) {
    ull r; asm("mov.b64 %0, {%1, %1};" : "=l"(r) : "f"(x)); return r;
}
__device__ __forceinline__ void ffma2(ull& d, ull a, ull b) {
    asm("fma.rn.f32x2 %0, %1, %2, %3;" : "=l"(d) : "l"(a), "l"(b), "l"(d));
}
__device__ __forceinline__ void unpack2(ull v, float& lo, float& hi) {
    asm("mov.b64 {%0, %1}, %2;" : "=f"(lo), "=f"(hi) : "l"(v));
}

// ---- C = A @ B (64x64), 512 threads, thread tile 2 rows x 4 cols.
// AT[k][i] = A[i][k] (transposed layout), Bsh[k][j] natural.
// A: LDS.64 broadcast; B: LDS.128 at 4*lane -> conflict-free.
__device__ __forceinline__ void gemmAT512(const float* __restrict__ AT,
                                          const float* __restrict__ Bsh,
                                          float* __restrict__ Csh,
                                          int tid, bool transC) {
    const int i0 = (tid >> 4) * 2;
    const int j0 = (tid & 15) * 4;
    ull a00 = 0, a01 = 0, a10 = 0, a11 = 0;
    #pragma unroll 8
    for (int k = 0; k < 64; k++) {
        float2 aq = *(const float2*)&AT[k * SP + i0];
        ulonglong2 bq = *(const ulonglong2*)&Bsh[k * SP + j0];
        ull p0 = pack2(aq.x), p1 = pack2(aq.y);
        ffma2(a00, p0, bq.x); ffma2(a01, p0, bq.y);
        ffma2(a10, p1, bq.x); ffma2(a11, p1, bq.y);
    }
    if (!transC) {
        ulonglong2 s0; s0.x = a00; s0.y = a01;
        ulonglong2 s1; s1.x = a10; s1.y = a11;
        *(ulonglong2*)&Csh[i0 * SP + j0]       = s0;
        *(ulonglong2*)&Csh[(i0 + 1) * SP + j0] = s1;
    } else {
        float v0[4], v1[4];
        unpack2(a00, v0[0], v0[1]); unpack2(a01, v0[2], v0[3]);
        unpack2(a10, v1[0], v1[1]); unpack2(a11, v1[2], v1[3]);
        #pragma unroll
        for (int c = 0; c < 4; c++) {
            float2 col = make_float2(v0[c], v1[c]);
            *(float2*)&Csh[(j0 + c) * SP + i0] = col;
        }
    }
}

// Dual GEMM sharing B: C1 = A1@B -> Csh, C2 = A2@B -> direct global rows
__device__ __forceinline__ void gemmATdual512(const float* __restrict__ AT1,
                                              const float* __restrict__ AT2,
                                              const float* __restrict__ Bsh,
                                              float* __restrict__ C1sh,
                                              float* __restrict__ C2g,  // row-major 64x64
                                              int tid) {
    const int i0 = (tid >> 4) * 2;
    const int j0 = (tid & 15) * 4;
    ull x00 = 0, x01 = 0, x10 = 0, x11 = 0;
    ull y00 = 0, y01 = 0, y10 = 0, y11 = 0;
    #pragma unroll 4
    for (int k = 0; k < 64; k++) {
        float2 aq = *(const float2*)&AT1[k * SP + i0];
        float2 cq = *(const float2*)&AT2[k * SP + i0];
        ulonglong2 bq = *(const ulonglong2*)&Bsh[k * SP + j0];
        ull p0 = pack2(aq.x), p1 = pack2(aq.y);
        ull q0 = pack2(cq.x), q1 = pack2(cq.y);
        ffma2(x00, p0, bq.x); ffma2(x01, p0, bq.y);
        ffma2(x10, p1, bq.x); ffma2(x11, p1, bq.y);
        ffma2(y00, q0, bq.x); ffma2(y01, q0, bq.y);
        ffma2(y10, q1, bq.x); ffma2(y11, q1, bq.y);
    }
    ulonglong2 s0; s0.x = x00; s0.y = x01;
    ulonglong2 s1; s1.x = x10; s1.y = x11;
    *(ulonglong2*)&C1sh[i0 * SP + j0]       = s0;
    *(ulonglong2*)&C1sh[(i0 + 1) * SP + j0] = s1;
    float4 w0, w1;
    unpack2(y00, w0.x, w0.y); unpack2(y01, w0.z, w0.w);
    unpack2(y10, w1.x, w1.y); unpack2(y11, w1.z, w1.w);
    *(float4*)&C2g[i0 * MS + j0]       = w0;
    *(float4*)&C2g[(i0 + 1) * MS + j0] = w1;
}

// ---------------- K1: per-batch setup (512 threads) -------------------------
#define K1_SMEM (6 * 64 * SP * 4)

__global__ void __launch_bounds__(512) mmf_k1(const float* __restrict__ A,
                                              const float* __restrict__ O,
                                              const int* __restrict__ idx,
                                              const int* __restrict__ wav) {
    extern __shared__ float sm[];
    float* Msh  = sm;
    float* MTsh = sm + 1 * 64 * SP;
    float* WMsh = sm + 2 * 64 * SP;
    float* BufA = sm + 3 * 64 * SP;
    float* BufB = sm + 4 * 64 * SP;
    float* BufC = sm + 5 * 64 * SP;

    __shared__ int slotof[Nn];
    __shared__ int slots[MS], val[MS], isf[MS], fpos[MS], pslot[MS], wflag[MS];
    __shared__ int rs[Kk];
    __shared__ float Osh[Kk * Kk];
    __shared__ float tmp[Kk * 64];

    const int b = blockIdx.x;
    const int tid = threadIdx.x;

    slotof[tid] = -1;
    if (tid < MS) { wflag[tid] = 0; slots[tid] = 0; val[tid] = idx[b * MS + tid]; }
    __syncthreads();

    // parallel first-occurrence dedup
    if (tid < MS) {
        int v = val[tid], fp = 0;
        while (val[fp] != v) fp++;
        fpos[tid] = fp;
        isf[tid] = (fp == tid) ? 1 : 0;
    }
    __syncthreads();
    if (tid < MS) {
        int s = 0, fp = fpos[tid];
        for (int q = 0; q < fp; q++) s += isf[q];
        pslot[tid] = s;
        if (isf[tid]) { slots[s] = val[tid]; slotof[val[tid]] = s; }
    }
    __syncthreads();
    if (tid < Ll) wflag[slotof[wav[b * Ll + tid]]] = 1;
    if (tid == 0) {
        int m = 0;
        #pragma unroll
        for (int q = 0; q < MS; q++) m += isf[q];
        g_m[b] = m;
    }
    __syncthreads();

    // M = I
    for (int e = tid; e < 4096; e += 512) {
        int i = e >> 6, j = e & 63;
        Msh[i * SP + j] = (i == j) ? 1.f : 0.f;
    }
    __syncthreads();

    // layer updates: rows pslot(l,:) <- O_l @ those rows
    for (int l = 0; l < Ll; l++) {
        if (tid < Kk) rs[tid] = pslot[l * Kk + tid];
        if (tid < Kk * Kk) Osh[tid] = O[((size_t)l * Bb + b) * Kk * Kk + tid];
        __syncthreads();
        {
            int i = tid >> 6, c = tid & 63;
            float s = 0.f;
            #pragma unroll
            for (int j = 0; j < Kk; j++) s += Osh[i * Kk + j] * Msh[rs[j] * SP + c];
            tmp[tid] = s;
        }
        __syncthreads();
        Msh[rs[tid >> 6] * SP + (tid & 63)] = tmp[tid];
        __syncthreads();
    }

    // MT + WM + publish maps
    for (int e = tid; e < 4096; e += 512) {
        int i = e >> 6, j = e & 63;
        float v = Msh[i * SP + j];
        MTsh[j * SP + i] = v;
        WMsh[i * SP + j] = wflag[i] ? 0.f : v;
        g_MT[b][j][i] = v;
    }
    g_slotof[b][tid] = (int8_t)slotof[tid];
    if (tid < MS) {
        g_slots[b][tid] = slots[tid];
        g_wflag[b][tid] = (int8_t)wflag[tid];
    }

    // BufA = A_RR gather
    for (int e = tid; e < 4096; e += 512) {
        int i = e >> 6, j = e & 63;
        BufA[i * SP + j] = A[((size_t)b * Nn + slots[i]) * Nn + slots[j]];
    }
    __syncthreads();

    // S1: X = M @ A_RR -> store X^T in BufB
    gemmAT512(MTsh, BufA, BufB, tid, true);  __syncthreads();
    // S2: F = X @ M^T  (AT = X^T, B = MT) -> BufC
    gemmAT512(BufB, MTsh, BufC, tid, false); __syncthreads();

    // mask -> D_RR (symmetric), publish
    for (int e = tid; e < 4096; e += 512) {
        int i = e >> 6, j = e & 63;
        float v = BufC[i * SP + j];
        if (i != j && (wflag[i] || wflag[j])) v = 0.f;
        BufC[i * SP + j] = v;
        g_DRR[b][i][j] = v;
    }
    __syncthreads();

    // S3 dual: T = D@M (AT=D symmetric) -> BufB ; P = (SM)^T@M (AT=WM) -> g_P
    gemmATdual512(BufC, WMsh, Msh, BufB, &g_P[b][0][0], tid);
    __syncthreads();
    // S4: G2 = M^T@T (AT=M, B=T) -> direct to g_G2
    {
        const int i0 = (tid >> 4) * 2;
        const int j0 = (tid & 15) * 4;
        ull a00 = 0, a01 = 0, a10 = 0, a11 = 0;
        #pragma unroll 8
        for (int k = 0; k < 64; k++) {
            float2 aq = *(const float2*)&Msh[k * SP + i0];
            ulonglong2 bq = *(const ulonglong2*)&BufB[k * SP + j0];
            ull p0 = pack2(aq.x), p1 = pack2(aq.y);
            ffma2(a00, p0, bq.x); ffma2(a01, p0, bq.y);
            ffma2(a10, p1, bq.x); ffma2(a11, p1, bq.y);
        }
        float4 w0, w1;
        unpack2(a00, w0.x, w0.y); unpack2(a01, w0.z, w0.w);
        unpack2(a10, w1.x, w1.y); unpack2(a11, w1.z, w1.w);
        *(float4*)&g_G2[b][i0][j0]     = w0;
        *(float4*)&g_G2[b][i0 + 1][j0] = w1;
    }
}

// ---------------- K2: strip dual-GEMM per 128-col tile (128 CTAs, 512 thr) --
#define K2_SMEM ((2 * 64 * SP + 3 * 64 * AS) * 4)

__global__ void __launch_bounds__(512) mmf_k2(const float* __restrict__ A,
                                              float* __restrict__ out) {
    extern __shared__ float sm2[];
    float* MTsh = sm2;
    float* Psh  = sm2 + 64 * SP;
    float* At   = sm2 + 2 * 64 * SP;
    float* Dsh  = At + 64 * AS;
    float* Esh  = Dsh + 64 * AS;

    __shared__ int    slots[MS];
    __shared__ int8_t wfl[MS];
    __shared__ int8_t slc[128];
    __shared__ int    mS;

    const int b  = blockIdx.y;
    const int c0 = blockIdx.x * 128;
    const int tid = threadIdx.x;

    for (int e = tid; e < 4096; e += 512) {
        int i = e >> 6, j = e & 63;
        MTsh[i * SP + j] = g_MT[b][i][j];
        Psh[i * SP + j]  = g_P[b][i][j];    // symmetric
    }
    if (tid < MS) { slots[tid] = g_slots[b][tid]; wfl[tid] = g_wflag[b][tid]; }
    if (tid >= 128 && tid < 256) slc[tid - 128] = g_slotof[b][c0 + (tid - 128)];
    if (tid == 0) mS = g_m[b];
    __syncthreads();

    // gather A strip tile (rows = slots), 64 x 128
    {
        int k = tid >> 3, cq = (tid & 7) * 16;
        const float* src = &A[((size_t)b * Nn + slots[k]) * Nn + c0 + cq];
        #pragma unroll
        for (int q = 0; q < 4; q++)
            *(float4*)&At[k * AS + cq + 4 * q] = *(const float4*)&src[4 * q];
    }
    __syncthreads();

    // dual GEMM: F = M @ At (via MT quads), E = P @ At (P symmetric)
    const int i0 = (tid >> 5) * 4;
    const int j0 = (tid & 31) * 4;
    ull aF[4][2], aE[4][2];
    #pragma unroll
    for (int r = 0; r < 4; r++) {
        aF[r][0] = aF[r][1] = 0ULL;
        aE[r][0] = aE[r][1] = 0ULL;
    }

    #pragma unroll 4
    for (int k = 0; k < 64; k++) {
        float4 mq = *(const float4*)&MTsh[k * SP + i0];   // broadcast
        float4 pq = *(const float4*)&Psh[k * SP + i0];    // broadcast
        ulonglong2 bq = *(const ulonglong2*)&At[k * AS + j0];
        ull m0 = pack2(mq.x), m1 = pack2(mq.y), m2 = pack2(mq.z), m3 = pack2(mq.w);
        ull p0 = pack2(pq.x), p1 = pack2(pq.y), p2 = pack2(pq.z), p3 = pack2(pq.w);
        ffma2(aF[0][0], m0, bq.x); ffma2(aF[0][1], m0, bq.y);
        ffma2(aF[1][0], m1, bq.x); ffma2(aF[1][1], m1, bq.y);
        ffma2(aF[2][0], m2, bq.x); ffma2(aF[2][1], m2, bq.y);
        ffma2(aF[3][0], m3, bq.x); ffma2(aF[3][1], m3, bq.y);
        ffma2(aE[0][0], p0, bq.x); ffma2(aE[0][1], p0, bq.y);
        ffma2(aE[1][0], p1, bq.x); ffma2(aE[1][1], p1, bq.y);
        ffma2(aE[2][0], p2, bq.x); ffma2(aE[2][1], p2, bq.y);
        ffma2(aE[3][0], p3, bq.x); ffma2(aE[3][1], p3, bq.y);
    }

    const size_t MAT = (size_t)Bb * Nn * Nn;
    const int s0 = slc[j0], s1 = slc[j0 + 1], s2 = slc[j0 + 2], s3 = slc[j0 + 3];

    #pragma unroll
    for (int r = 0; r < 4; r++) {
        const int i = i0 + r;
        const float wz = wfl[i] ? 0.f : 1.f;
        float f0, f1, f2, f3, e0, e1, e2, e3;
        unpack2(aF[r][0], f0, f1); unpack2(aF[r][1], f2, f3);
        unpack2(aE[r][0], e0, e1); unpack2(aE[r][1], e2, e3);

        float4 dv, av, rv;
        dv.x = (s0 >= 0) ? g_DRR[b][i][s0] : wz * f0;
        dv.y = (s1 >= 0) ? g_DRR[b][i][s1] : wz * f1;
        dv.z = (s2 >= 0) ? g_DRR[b][i][s2] : wz * f2;
        dv.w = (s3 >= 0) ? g_DRR[b][i][s3] : wz * f3;
        av.x = (s0 >= 0) ? g_G2[b][i][s0] : e0;
        av.y = (s1 >= 0) ? g_G2[b][i][s1] : e1;
        av.z = (s2 >= 0) ? g_G2[b][i][s2] : e2;
        av.w = (s3 >= 0) ? g_G2[b][i][s3] : e3;
        rv.x = (s0 >= 0) ? MTsh[s0 * SP + i] : 0.f;
        rv.y = (s1 >= 0) ? MTsh[s1 * SP + i] : 0.f;
        rv.z = (s2 >= 0) ? MTsh[s2 * SP + i] : 0.f;
        rv.w = (s3 >= 0) ? MTsh[s3 * SP + i] : 0.f;

        *(float4*)&Dsh[i * AS + j0] = dv;
        *(float4*)&Esh[i * AS + j0] = av;
        if (i < mS) {
            const size_t base = ((size_t)b * Nn + slots[i]) * Nn + c0 + j0;
            __stcs((float4*)&out[base],           av);   // A_rec
            __stcs((float4*)&out[MAT + base],     rv);   // right
            __stcs((float4*)&out[2 * MAT + base], dv);   // D
        }
    }
    __syncthreads();

    // coalesced transposed copies for K3 column patching
    for (int e = tid; e < 8192; e += 512) {
        int cc = e >> 6, rr = e & 63;
        g_DcolT[b][c0 + cc][rr] = Dsh[rr * AS + cc];
        g_AcolT[b][c0 + cc][rr] = Esh[rr * AS + cc];
    }
}

// ---------------- K3: non-strip rows assembly --------------------------------
__global__ void __launch_bounds__(512) mmf_k3(const float* __restrict__ A,
                                              float* __restrict__ out) {
    const int b    = blockIdx.y;
    const int i    = blockIdx.x * 4 + (threadIdx.x >> 7);
    const int lane = threadIdx.x & 127;
    const int c0   = lane * 4;

    if (g_slotof[b][i] >= 0) return;   // strip rows written by K2

    const size_t rowbase = ((size_t)b * Nn + i) * Nn + c0;
    const char4 sl = *(const char4*)(&g_slotof[b][c0]);

    float4 a = __ldcs((const float4*)&A[rowbase]);
    float4 va = a, vd = a;
    const float* act = &g_AcolT[b][i][0];
    const float* dct = &g_DcolT[b][i][0];
    if (sl.x >= 0) { va.x = act[sl.x]; vd.x = dct[sl.x]; }
    if (sl.y >= 0) { va.y = act[sl.y]; vd.y = dct[sl.y]; }
    if (sl.z >= 0) { va.z = act[sl.z]; vd.z = dct[sl.z]; }
    if (sl.w >= 0) { va.w = act[sl.w]; vd.w = dct[sl.w]; }
    float4 vr = make_float4(0.f, 0.f, 0.f, 0.f);
    if (i >= c0 && i < c0 + 4) ((float*)&vr)[i - c0] = 1.f;

    const size_t MAT = (size_t)Bb * Nn * Nn;
    __stcs((float4*)&out[rowbase],           va);
    __stcs((float4*)&out[MAT + rowbase],     vr);
    __stcs((float4*)&out[2 * MAT + rowbase], vd);
}

// ---------------- launch ------------------------------------------------------
extern "C" void kernel_launch(void* const* d_in, const int* in_sizes, int n_in,
                              void* d_out, int out_size) {
    const float* A   = (const float*)d_in[0];
    const float* O   = (const float*)d_in[1];
    const int*   idx = (const int*)d_in[2];
    const int*   wav = (const int*)d_in[3];
    float* out = (float*)d_out;

    cudaFuncSetAttribute(mmf_k1, cudaFuncAttributeMaxDynamicSharedMemorySize, K1_SMEM);
    cudaFuncSetAttribute(mmf_k2, cudaFuncAttributeMaxDynamicSharedMemorySize, K2_SMEM);

    mmf_k1<<<Bb, 512, K1_SMEM>>>(A, O, idx, wav);
    mmf_k2<<<dim3(Nn / 128, Bb), 512, K2_SMEM>>>(A, out);
    mmf_k3<<<dim3(Nn / 4, Bb), 512>>>(A, out);
}

// round 6
// speedup vs baseline: 2.3033x; 1.1388x over previous
#include <cuda_runtime.h>
#include <stdint.h>

#define Bb 32
#define Nn 512
#define Ll 8
#define Kk 8
#define MS 64
#define SP 68    // 64-wide shared stride: conflict-free, 16B-aligned rows
#define AS 132   // 128-wide shared stride: conflict-free, 16B-aligned rows

// ---------------- scratch (static device globals) ---------------------------
__device__ float  g_MT[Bb][MS][MS];     // MT[i][j] = M[j][i]
__device__ float  g_P[Bb][MS][MS];      // M^T diag(~w) M (symmetric)
__device__ float  g_DRR[Bb][MS][MS];
__device__ float  g_G2[Bb][MS][MS];
__device__ float  g_DcolT[Bb][Nn][MS];
__device__ float  g_AcolT[Bb][Nn][MS];
__device__ int8_t g_slotof[Bb][Nn];
__device__ int    g_slots[Bb][MS];
__device__ int8_t g_wflag[Bb][MS];
__device__ int    g_m[Bb];

// ---------------- packed f32x2 helpers --------------------------------------
typedef unsigned long long ull;

__device__ __forceinline__ ull pack2(float x) {
    ull r; asm("mov.b64 %0, {%1, %1};" : "=l"(r) : "f"(x)); return r;
}
__device__ __forceinline__ void ffma2(ull& d, ull a, ull b) {
    asm("fma.rn.f32x2 %0, %1, %2, %3;" : "=l"(d) : "l"(a), "l"(b), "l"(d));
}
__device__ __forceinline__ void unpack2(ull v, float& lo, float& hi) {
    asm("mov.b64 {%0, %1}, %2;" : "=f"(lo), "=f"(hi) : "l"(v));
}

// ---- C = A @ B (64x64), 512 threads, thread tile 2 rows x 4 cols.
// AT[k][i] = A[i][k]; Bsh[k][j] natural. Conflict-free.
__device__ __forceinline__ void gemmAT512(const float* __restrict__ AT,
                                          const float* __restrict__ Bsh,
                                          float* __restrict__ Csh, int tid) {
    const int i0 = (tid >> 4) * 2;
    const int j0 = (tid & 15) * 4;
    ull a00 = 0, a01 = 0, a10 = 0, a11 = 0;
    #pragma unroll 8
    for (int k = 0; k < 64; k++) {
        float2 aq = *(const float2*)&AT[k * SP + i0];
        ulonglong2 bq = *(const ulonglong2*)&Bsh[k * SP + j0];
        ull p0 = pack2(aq.x), p1 = pack2(aq.y);
        ffma2(a00, p0, bq.x); ffma2(a01, p0, bq.y);
        ffma2(a10, p1, bq.x); ffma2(a11, p1, bq.y);
    }
    ulonglong2 s0; s0.x = a00; s0.y = a01;
    ulonglong2 s1; s1.x = a10; s1.y = a11;
    *(ulonglong2*)&Csh[i0 * SP + j0]       = s0;
    *(ulonglong2*)&Csh[(i0 + 1) * SP + j0] = s1;
}

// Dual GEMM sharing B: C1 = A1@B -> smem, C2 = A2@B -> global (row-major 64x64)
__device__ __forceinline__ void gemmATdual512(const float* __restrict__ AT1,
                                              const float* __restrict__ AT2,
                                              const float* __restrict__ Bsh,
                                              float* __restrict__ C1sh,
                                              float* __restrict__ C2g, int tid) {
    const int i0 = (tid >> 4) * 2;
    const int j0 = (tid & 15) * 4;
    ull x00 = 0, x01 = 0, x10 = 0, x11 = 0;
    ull y00 = 0, y01 = 0, y10 = 0, y11 = 0;
    #pragma unroll 4
    for (int k = 0; k < 64; k++) {
        float2 aq = *(const float2*)&AT1[k * SP + i0];
        float2 cq = *(const float2*)&AT2[k * SP + i0];
        ulonglong2 bq = *(const ulonglong2*)&Bsh[k * SP + j0];
        ull p0 = pack2(aq.x), p1 = pack2(aq.y);
        ull q0 = pack2(cq.x), q1 = pack2(cq.y);
        ffma2(x00, p0, bq.x); ffma2(x01, p0, bq.y);
        ffma2(x10, p1, bq.x); ffma2(x11, p1, bq.y);
        ffma2(y00, q0, bq.x); ffma2(y01, q0, bq.y);
        ffma2(y10, q1, bq.x); ffma2(y11, q1, bq.y);
    }
    ulonglong2 s0; s0.x = x00; s0.y = x01;
    ulonglong2 s1; s1.x = x10; s1.y = x11;
    *(ulonglong2*)&C1sh[i0 * SP + j0]       = s0;
    *(ulonglong2*)&C1sh[(i0 + 1) * SP + j0] = s1;
    float4 w0, w1;
    unpack2(y00, w0.x, w0.y); unpack2(y01, w0.z, w0.w);
    unpack2(y10, w1.x, w1.y); unpack2(y11, w1.z, w1.w);
    *(float4*)&C2g[i0 * MS + j0]       = w0;
    *(float4*)&C2g[(i0 + 1) * MS + j0] = w1;
}

// ---------------- K1: per-batch setup (512 threads, ~10 barriers) -----------
#define K1_SMEM (6 * 64 * SP * 4)

__global__ void __launch_bounds__(512) mmf_k1(const float* __restrict__ A,
                                              const float* __restrict__ O,
                                              const int* __restrict__ idx,
                                              const int* __restrict__ wav) {
    extern __shared__ float sm[];
    float* Msh  = sm;
    float* MTsh = sm + 1 * 64 * SP;
    float* WMsh = sm + 2 * 64 * SP;
    float* BufA = sm + 3 * 64 * SP;   // A_RR, then T
    float* BufB = sm + 4 * 64 * SP;   // Y = X^T, then T
    float* BufC = sm + 5 * 64 * SP;   // F -> D_RR

    __shared__ int   slotof[Nn];
    __shared__ int   slots[MS], val[MS], isf[MS], pslot[MS], wflag[MS];
    __shared__ float OshAll[Ll * MS];   // all 8 layer O matrices (8x64)

    const int b   = blockIdx.x;
    const int tid = threadIdx.x;
    const int wid = tid >> 5;
    const int lid = tid & 31;

    // ---- phase A: init + loads -------------------------------------------
    slotof[tid] = -1;
    if (tid < MS) { wflag[tid] = 0; val[tid] = idx[b * MS + tid]; }
    OshAll[tid] = O[(size_t)(tid >> 6) * Bb * MS + (size_t)b * MS + (tid & 63)];
    // M = I
    for (int e = tid; e < 4096; e += 512) {
        int i = e >> 6, j = e & 63;
        Msh[i * SP + j] = (i == j) ? 1.f : 0.f;
    }
    __syncthreads();

    // ---- phase B: pipelined dedup ------------------------------------------
    if (tid < MS) {
        const int v = val[tid];
        int fp = MS;
        #pragma unroll 8
        for (int q = MS - 1; q >= 0; q--) if (val[q] == v) fp = q;
        isf[tid] = (fp == tid) ? 1 : 0;
        pslot[tid] = fp;   // temporarily store fp
    }
    __syncthreads();
    if (tid < MS) {
        const int fp = pslot[tid];
        int s = 0;
        #pragma unroll 8
        for (int q = 0; q < MS; q++) s += (q < fp) ? isf[q] : 0;
        pslot[tid] = s;
        if (isf[tid]) { slots[s] = val[tid]; slotof[val[tid]] = s; }
    }
    __syncthreads();
    if (tid < Ll) wflag[slotof[wav[b * Ll + tid]]] = 1;
    if (tid == 256) {
        int m = 0;
        #pragma unroll
        for (int q = 0; q < MS; q++) m += isf[q];
        g_m[b] = m;
    }
    __syncthreads();

    // ---- phase C: warp 0 builds M; warps 1-15 gather A_RR + publish --------
    if (wid == 0) {
        // one-warp layer loop, syncwarp only
        for (int l = 0; l < Ll; l++) {
            int rsv[Kk];
            #pragma unroll
            for (int j = 0; j < Kk; j++) rsv[j] = pslot[l * Kk + j];
            float acc0[Kk], acc1[Kk];
            #pragma unroll
            for (int i = 0; i < Kk; i++) { acc0[i] = 0.f; acc1[i] = 0.f; }
            #pragma unroll
            for (int j = 0; j < Kk; j++) {
                const float m0 = Msh[rsv[j] * SP + lid];
                const float m1 = Msh[rsv[j] * SP + lid + 32];
                #pragma unroll
                for (int i = 0; i < Kk; i++) {
                    const float o = OshAll[l * MS + i * Kk + j];
                    acc0[i] += o * m0;
                    acc1[i] += o * m1;
                }
            }
            __syncwarp();
            #pragma unroll
            for (int i = 0; i < Kk; i++) {
                Msh[rsv[i] * SP + lid]      = acc0[i];
                Msh[rsv[i] * SP + lid + 32] = acc1[i];
            }
            __syncwarp();
        }
    } else {
        const int t = tid - 32;   // 0..479
        // gather A_RR
        for (int e = t; e < 4096; e += 480) {
            int i = e >> 6, j = e & 63;
            BufA[i * SP + j] = A[((size_t)b * Nn + slots[i]) * Nn + slots[j]];
        }
        // publish maps
        for (int j = t; j < Nn; j += 480) g_slotof[b][j] = (int8_t)slotof[j];
        if (t < MS) {
            g_slots[b][t] = slots[t];
            g_wflag[b][t] = (int8_t)wflag[t];
        }
    }
    __syncthreads();

    // ---- phase D: MT, WM, publish MT (coalesced) ---------------------------
    for (int e = tid; e < 4096; e += 512) {
        int i = e >> 6, j = e & 63;
        float v = Msh[i * SP + j];
        MTsh[j * SP + i] = v;
        WMsh[i * SP + j] = wflag[i] ? 0.f : v;
    }
    __syncthreads();
    for (int e = tid; e < 4096; e += 512)
        g_MT[b][e >> 6][e & 63] = MTsh[(e >> 6) * SP + (e & 63)];

    // ---- phase E: GEMM chain ------------------------------------------------
    // S1: Y = A_RR @ M^T  (= X^T; A_RR symmetric -> AT = BufA; B[k][j]=M[j][k]=MTsh)
    gemmAT512(BufA, MTsh, BufB, tid);  __syncthreads();
    // S2: F = M @ Y   (AT[k][i]=M[i][k]=MTsh; B = Y)
    gemmAT512(MTsh, BufB, BufC, tid);  __syncthreads();

    // mask -> D_RR (symmetric), publish
    for (int e = tid; e < 4096; e += 512) {
        int i = e >> 6, j = e & 63;
        float v = BufC[i * SP + j];
        if (i != j && (wflag[i] || wflag[j])) v = 0.f;
        BufC[i * SP + j] = v;
        g_DRR[b][i][j] = v;
    }
    __syncthreads();

    // S3 dual: T = D@M (D sym -> AT=BufC, B=Msh) -> BufB ; P = (WM)^T@M -> g_P
    gemmATdual512(BufC, WMsh, Msh, BufB, &g_P[b][0][0], tid);
    __syncthreads();

    // S4: G2 = M^T @ T (AT[k][i]=M[k][i]=Msh; B=T) -> direct to g_G2
    {
        const int i0 = (tid >> 4) * 2;
        const int j0 = (tid & 15) * 4;
        ull a00 = 0, a01 = 0, a10 = 0, a11 = 0;
        #pragma unroll 8
        for (int k = 0; k < 64; k++) {
            float2 aq = *(const float2*)&Msh[k * SP + i0];
            ulonglong2 bq = *(const ulonglong2*)&BufB[k * SP + j0];
            ull p0 = pack2(aq.x), p1 = pack2(aq.y);
            ffma2(a00, p0, bq.x); ffma2(a01, p0, bq.y);
            ffma2(a10, p1, bq.x); ffma2(a11, p1, bq.y);
        }
        float4 w0, w1;
        unpack2(a00, w0.x, w0.y); unpack2(a01, w0.z, w0.w);
        unpack2(a10, w1.x, w1.y); unpack2(a11, w1.z, w1.w);
        *(float4*)&g_G2[b][i0][j0]     = w0;
        *(float4*)&g_G2[b][i0 + 1][j0] = w1;
    }
}

// ---------------- K2: strip dual-GEMM per 128-col tile (128 CTAs, 512 thr) --
#define K2_SMEM ((2 * 64 * SP + 3 * 64 * AS) * 4)

__global__ void __launch_bounds__(512) mmf_k2(const float* __restrict__ A,
                                              float* __restrict__ out) {
    extern __shared__ float sm2[];
    float* MTsh = sm2;
    float* Psh  = sm2 + 64 * SP;
    float* At   = sm2 + 2 * 64 * SP;
    float* Dsh  = At + 64 * AS;
    float* Esh  = Dsh + 64 * AS;

    __shared__ int    slots[MS];
    __shared__ int8_t wfl[MS];
    __shared__ int8_t slc[128];
    __shared__ int    mS;

    const int b  = blockIdx.y;
    const int c0 = blockIdx.x * 128;
    const int tid = threadIdx.x;

    for (int e = tid; e < 4096; e += 512) {
        int i = e >> 6, j = e & 63;
        MTsh[i * SP + j] = g_MT[b][i][j];
        Psh[i * SP + j]  = g_P[b][i][j];    // symmetric
    }
    if (tid < MS) { slots[tid] = g_slots[b][tid]; wfl[tid] = g_wflag[b][tid]; }
    if (tid >= 128 && tid < 256) slc[tid - 128] = g_slotof[b][c0 + (tid - 128)];
    if (tid == 0) mS = g_m[b];
    __syncthreads();

    // gather A strip tile (rows = slots), 64 x 128
    {
        int k = tid >> 3, cq = (tid & 7) * 16;
        const float* src = &A[((size_t)b * Nn + slots[k]) * Nn + c0 + cq];
        #pragma unroll
        for (int q = 0; q < 4; q++)
            *(float4*)&At[k * AS + cq + 4 * q] = *(const float4*)&src[4 * q];
    }
    __syncthreads();

    // dual GEMM: F = M @ At (via MT quads), E = P @ At (P symmetric)
    const int i0 = (tid >> 5) * 4;
    const int j0 = (tid & 31) * 4;
    ull aF[4][2], aE[4][2];
    #pragma unroll
    for (int r = 0; r < 4; r++) {
        aF[r][0] = aF[r][1] = 0ULL;
        aE[r][0] = aE[r][1] = 0ULL;
    }

    #pragma unroll 4
    for (int k = 0; k < 64; k++) {
        float4 mq = *(const float4*)&MTsh[k * SP + i0];   // broadcast
        float4 pq = *(const float4*)&Psh[k * SP + i0];    // broadcast
        ulonglong2 bq = *(const ulonglong2*)&At[k * AS + j0];
        ull m0 = pack2(mq.x), m1 = pack2(mq.y), m2 = pack2(mq.z), m3 = pack2(mq.w);
        ull p0 = pack2(pq.x), p1 = pack2(pq.y), p2 = pack2(pq.z), p3 = pack2(pq.w);
        ffma2(aF[0][0], m0, bq.x); ffma2(aF[0][1], m0, bq.y);
        ffma2(aF[1][0], m1, bq.x); ffma2(aF[1][1], m1, bq.y);
        ffma2(aF[2][0], m2, bq.x); ffma2(aF[2][1], m2, bq.y);
        ffma2(aF[3][0], m3, bq.x); ffma2(aF[3][1], m3, bq.y);
        ffma2(aE[0][0], p0, bq.x); ffma2(aE[0][1], p0, bq.y);
        ffma2(aE[1][0], p1, bq.x); ffma2(aE[1][1], p1, bq.y);
        ffma2(aE[2][0], p2, bq.x); ffma2(aE[2][1], p2, bq.y);
        ffma2(aE[3][0], p3, bq.x); ffma2(aE[3][1], p3, bq.y);
    }

    const size_t MAT = (size_t)Bb * Nn * Nn;
    const int s0 = slc[j0], s1 = slc[j0 + 1], s2 = slc[j0 + 2], s3 = slc[j0 + 3];

    #pragma unroll
    for (int r = 0; r < 4; r++) {
        const int i = i0 + r;
        const float wz = wfl[i] ? 0.f : 1.f;
        float f0, f1, f2, f3, e0, e1, e2, e3;
        unpack2(aF[r][0], f0, f1); unpack2(aF[r][1], f2, f3);
        unpack2(aE[r][0], e0, e1); unpack2(aE[r][1], e2, e3);

        float4 dv, av, rv;
        dv.x = (s0 >= 0) ? g_DRR[b][i][s0] : wz * f0;
        dv.y = (s1 >= 0) ? g_DRR[b][i][s1] : wz * f1;
        dv.z = (s2 >= 0) ? g_DRR[b][i][s2] : wz * f2;
        dv.w = (s3 >= 0) ? g_DRR[b][i][s3] : wz * f3;
        av.x = (s0 >= 0) ? g_G2[b][i][s0] : e0;
        av.y = (s1 >= 0) ? g_G2[b][i][s1] : e1;
        av.z = (s2 >= 0) ? g_G2[b][i][s2] : e2;
        av.w = (s3 >= 0) ? g_G2[b][i][s3] : e3;
        rv.x = (s0 >= 0) ? MTsh[s0 * SP + i] : 0.f;
        rv.y = (s1 >= 0) ? MTsh[s1 * SP + i] : 0.f;
        rv.z = (s2 >= 0) ? MTsh[s2 * SP + i] : 0.f;
        rv.w = (s3 >= 0) ? MTsh[s3 * SP + i] : 0.f;

        *(float4*)&Dsh[i * AS + j0] = dv;
        *(float4*)&Esh[i * AS + j0] = av;
        if (i < mS) {
            const size_t base = ((size_t)b * Nn + slots[i]) * Nn + c0 + j0;
            __stcs((float4*)&out[base],           av);   // A_rec
            __stcs((float4*)&out[MAT + base],     rv);   // right
            __stcs((float4*)&out[2 * MAT + base], dv);   // D
        }
    }
    __syncthreads();

    // coalesced transposed copies for K3 column patching
    for (int e = tid; e < 8192; e += 512) {
        int cc = e >> 6, rr = e & 63;
        g_DcolT[b][c0 + cc][rr] = Dsh[rr * AS + cc];
        g_AcolT[b][c0 + cc][rr] = Esh[rr * AS + cc];
    }
}

// ---------------- K3: non-strip rows assembly --------------------------------
__global__ void __launch_bounds__(512) mmf_k3(const float* __restrict__ A,
                                              float* __restrict__ out) {
    const int b    = blockIdx.y;
    const int i    = blockIdx.x * 4 + (threadIdx.x >> 7);
    const int lane = threadIdx.x & 127;
    const int c0   = lane * 4;

    if (g_slotof[b][i] >= 0) return;   // strip rows written by K2

    const size_t rowbase = ((size_t)b * Nn + i) * Nn + c0;
    const char4 sl = *(const char4*)(&g_slotof[b][c0]);

    float4 a = __ldcs((const float4*)&A[rowbase]);
    float4 va = a, vd = a;
    const float* act = &g_AcolT[b][i][0];
    const float* dct = &g_DcolT[b][i][0];
    if (sl.x >= 0) { va.x = act[sl.x]; vd.x = dct[sl.x]; }
    if (sl.y >= 0) { va.y = act[sl.y]; vd.y = dct[sl.y]; }
    if (sl.z >= 0) { va.z = act[sl.z]; vd.z = dct[sl.z]; }
    if (sl.w >= 0) { va.w = act[sl.w]; vd.w = dct[sl.w]; }
    float4 vr = make_float4(0.f, 0.f, 0.f, 0.f);
    if (i >= c0 && i < c0 + 4) ((float*)&vr)[i - c0] = 1.f;

    const size_t MAT = (size_t)Bb * Nn * Nn;
    __stcs((float4*)&out[rowbase],           va);
    __stcs((float4*)&out[MAT + rowbase],     vr);
    __stcs((float4*)&out[2 * MAT + rowbase], vd);
}

// ---------------- launch ------------------------------------------------------
extern "C" void kernel_launch(void* const* d_in, const int* in_sizes, int n_in,
                              void* d_out, int out_size) {
    const float* A   = (const float*)d_in[0];
    const float* O   = (const float*)d_in[1];
    const int*   idx = (const int*)d_in[2];
    const int*   wav = (const int*)d_in[3];
    float* out = (float*)d_out;

    cudaFuncSetAttribute(mmf_k1, cudaFuncAttributeMaxDynamicSharedMemorySize, K1_SMEM);
    cudaFuncSetAttribute(mmf_k2, cudaFuncAttributeMaxDynamicSharedMemorySize, K2_SMEM);

    mmf_k1<<<Bb, 512, K1_SMEM>>>(A, O, idx, wav);
    mmf_k2<<<dim3(Nn / 128, Bb), 512, K2_SMEM>>>(A, out);
    mmf_k3<<<dim3(Nn / 4, Bb), 512>>>(A, out);
}